// round 14
// baseline (speedup 1.0000x reference)
#include <cuda_runtime.h>
#include <cuda_bf16.h>
#include <cuda_fp16.h>
#include <math.h>

// Output contract (proven): float32 indices, [0,1600) pred_idx, [1600,3200) tgt_idx.
// R13 finding: inputs are HOST-resident (C2C ~210GB/s); stage to HBM once.

#define Bsz 8
#define Qn  500
#define Tn  200
#define HWn 65536
#define OUT_ELEMS (2 * Bsz * Tn)
#define HALF      (Bsz * Tn)
#define KSPLIT 4
#define KSC (HWn / KSPLIT)         // 16384 k per split
#define COST_N (Bsz * Tn * Qn)     // 800000

#define BM 64                       // q tile
#define BN 64                       // t tile
#define BKT 32                      // k tile (floats)
#define LDA (BKT + 4)               // 36: padded smem stride
#define NTILES (KSC / BKT)          // 512
#define FOLDT 8

#define PRED_ELEMS ((size_t)Bsz * Qn * HWn)   // 262,144,000
#define TGT_ELEMS  ((size_t)Bsz * Tn * HWn)   // 104,857,600

__device__ float g_cost[COST_N];
__device__ float g_partial[KSPLIT][COST_N];
__device__ int   g_mode;                     // 0=fp32, 1=bf16, 2=fp16

// HBM staging for host-resident inputs (raw bytes, dtype-agnostic).
__device__ __align__(16) unsigned char g_predS[PRED_ELEMS * 4];
__device__ __align__(16) unsigned char g_tgtS [TGT_ELEMS  * 4];

__device__ __forceinline__ float fsigmoid(float x) {
    return __fdividef(1.0f, 1.0f + __expf(-x));
}
__device__ __forceinline__ unsigned tf32_of(float x) {
    unsigned r;
    asm("cvt.rna.tf32.f32 %0, %1;" : "=r"(r) : "f"(x));
    return r;
}

// --------------------------- dtype detector --------------------------------
#define DET_WORDS 16384
__global__ void detect_kernel(const void* tgt) {
    __shared__ int s_bf, s_fh;
    if (threadIdx.x == 0) { s_bf = 0; s_fh = 0; }
    __syncthreads();
    const unsigned int* w = (const unsigned int*)tgt;
    int bf = 0, fh = 0;
    for (int i = threadIdx.x; i < DET_WORDS; i += 256) {
        const unsigned int b1 = (w[i] >> 8) & 0xff;
        if (b1 == 0x3E || b1 == 0x3F) bf++;
        else if (b1 >= 0x30 && b1 <= 0x3B) fh++;
    }
    atomicAdd(&s_bf, bf);
    atomicAdd(&s_fh, fh);
    __syncthreads();
    if (threadIdx.x == 0) {
        if      (s_bf > DET_WORDS / 2) g_mode = 1;
        else if (s_fh > DET_WORDS / 2) g_mode = 2;
        else                           g_mode = 0;
    }
}

__global__ void zero_out_kernel(float* out, int n) {
    int i = blockIdx.x * blockDim.x + threadIdx.x;
    if (i < n) out[i] = 0.0f;
}

// ------------------------------ staging ------------------------------------
// Copy host-resident input to HBM, one pass, float4-wide.  Byte count depends
// on runtime dtype (mode).  which: 0 = pred, 1 = tgt.
__global__ void stage_kernel(const void* __restrict__ src, int which, long long nElems) {
    const int esz = (g_mode == 0) ? 4 : 2;
    const long long n16 = nElems * esz / 16;
    const float4* __restrict__ s = (const float4*)src;
    float4* __restrict__ d = (float4*)(which ? g_tgtS : g_predS);
    const long long stride = (long long)gridDim.x * blockDim.x;
    for (long long i = (long long)blockIdx.x * blockDim.x + threadIdx.x; i < n16; i += stride)
        d[i] = s[i];
}

template <int MODE>
__device__ __forceinline__ float4 load4(const void* base, size_t elemIdx) {
    if (MODE == 0) {
        return *(const float4*)((const float*)base + elemIdx);
    } else if (MODE == 1) {
        const __nv_bfloat162* p = (const __nv_bfloat162*)((const __nv_bfloat16*)base + elemIdx);
        const __nv_bfloat162 a = p[0], b = p[1];
        return make_float4(__bfloat162float(a.x), __bfloat162float(a.y),
                           __bfloat162float(b.x), __bfloat162float(b.y));
    } else {
        const __half2* p = (const __half2*)((const __half*)base + elemIdx);
        const __half2 a = p[0], b = p[1];
        return make_float4(__half2float(a.x), __half2float(a.y),
                           __half2float(b.x), __half2float(b.y));
    }
}

__device__ __forceinline__ void mma_tf32(float c[4], const unsigned a[4], const unsigned b[2]) {
    asm volatile(
        "mma.sync.aligned.m16n8k8.row.col.f32.tf32.tf32.f32 "
        "{%0,%1,%2,%3}, {%4,%5,%6,%7}, {%8,%9}, {%0,%1,%2,%3};"
        : "+f"(c[0]), "+f"(c[1]), "+f"(c[2]), "+f"(c[3])
        : "r"(a[0]), "r"(a[1]), "r"(a[2]), "r"(a[3]), "r"(b[0]), "r"(b[1]));
}

// ------------------------------ cost GEMM (3xTF32) -------------------------
// Reads the HBM-staged copies.  Grid (8, 4, Bsz*KSPLIT).
template <int MODE>
__device__ void cost_body() {
    const void* __restrict__ pred = (const void*)g_predS;
    const void* __restrict__ tgt  = (const void*)g_tgtS;

    __shared__ float Ah[BM][LDA], Al[BM][LDA];
    __shared__ float Bh[BN][LDA], Bl[BN][LDA];

    const int b  = blockIdx.z / KSPLIT;
    const int ks = blockIdx.z % KSPLIT;
    const int q0 = blockIdx.x * BM;
    const int t0 = blockIdx.y * BN;
    const int tid  = threadIdx.x;
    const int lane = tid & 31;
    const int warp = tid >> 5;
    const int wq = warp & 1;
    const int wt = warp >> 1;
    const int g    = lane >> 2;
    const int tid4 = lane & 3;

    const int lrow0 = tid >> 3;
    const int lrow1 = lrow0 + 32;
    const int lk4   = (tid & 7) * 4;
    const bool av0 = (q0 + lrow0) < Qn, av1 = (q0 + lrow1) < Qn;
    const bool bv0 = (t0 + lrow0) < Tn, bv1 = (t0 + lrow1) < Tn;
    const size_t kbase = (size_t)ks * KSC + lk4;
    const size_t aB0 = ((size_t)b * Qn + (av0 ? (q0 + lrow0) : 0)) * HWn + kbase;
    const size_t aB1 = ((size_t)b * Qn + (av1 ? (q0 + lrow1) : 0)) * HWn + kbase;
    const size_t bB0 = ((size_t)b * Tn + (bv0 ? (t0 + lrow0) : 0)) * HWn + kbase;
    const size_t bB1 = ((size_t)b * Tn + (bv1 ? (t0 + lrow1) : 0)) * HWn + kbase;

    float cc[2][2][4];
    float facc[2][2][4];
#pragma unroll
    for (int i = 0; i < 2; i++)
#pragma unroll
        for (int j = 0; j < 2; j++)
#pragma unroll
            for (int r = 0; r < 4; r++) { cc[i][j][r] = 0.0f; facc[i][j][r] = 0.0f; }

    float4 pa0 = av0 ? load4<MODE>(pred, aB0) : make_float4(0,0,0,0);
    float4 pa1 = av1 ? load4<MODE>(pred, aB1) : make_float4(0,0,0,0);
    float4 pb0 = bv0 ? load4<MODE>(tgt,  bB0) : make_float4(0,0,0,0);
    float4 pb1 = bv1 ? load4<MODE>(tgt,  bB1) : make_float4(0,0,0,0);

    for (int t = 0; t < NTILES; t++) {
        float s0x=0,s0y=0,s0z=0,s0w=0, s1x=0,s1y=0,s1z=0,s1w=0;
        if (av0) { s0x=fsigmoid(pa0.x); s0y=fsigmoid(pa0.y); s0z=fsigmoid(pa0.z); s0w=fsigmoid(pa0.w); }
        if (av1) { s1x=fsigmoid(pa1.x); s1y=fsigmoid(pa1.y); s1z=fsigmoid(pa1.z); s1w=fsigmoid(pa1.w); }

        __syncthreads();
        {
            float* ah0 = &Ah[lrow0][lk4]; float* al0 = &Al[lrow0][lk4];
            float* ah1 = &Ah[lrow1][lk4]; float* al1 = &Al[lrow1][lk4];
#define SPLIT_ST(dsth, dstl, v, idx) { unsigned h = tf32_of(v); float hf = __uint_as_float(h); \
        (dsth)[idx] = hf; (dstl)[idx] = __uint_as_float(tf32_of((v) - hf)); }
            SPLIT_ST(ah0, al0, s0x, 0) SPLIT_ST(ah0, al0, s0y, 1)
            SPLIT_ST(ah0, al0, s0z, 2) SPLIT_ST(ah0, al0, s0w, 3)
            SPLIT_ST(ah1, al1, s1x, 0) SPLIT_ST(ah1, al1, s1y, 1)
            SPLIT_ST(ah1, al1, s1z, 2) SPLIT_ST(ah1, al1, s1w, 3)
            float* bh0 = &Bh[lrow0][lk4]; float* bl0 = &Bl[lrow0][lk4];
            float* bh1 = &Bh[lrow1][lk4]; float* bl1 = &Bl[lrow1][lk4];
            float t0x = bv0?pb0.x:0, t0y = bv0?pb0.y:0, t0z = bv0?pb0.z:0, t0w = bv0?pb0.w:0;
            float t1x = bv1?pb1.x:0, t1y = bv1?pb1.y:0, t1z = bv1?pb1.z:0, t1w = bv1?pb1.w:0;
            SPLIT_ST(bh0, bl0, t0x, 0) SPLIT_ST(bh0, bl0, t0y, 1)
            SPLIT_ST(bh0, bl0, t0z, 2) SPLIT_ST(bh0, bl0, t0w, 3)
            SPLIT_ST(bh1, bl1, t1x, 0) SPLIT_ST(bh1, bl1, t1y, 1)
            SPLIT_ST(bh1, bl1, t1z, 2) SPLIT_ST(bh1, bl1, t1w, 3)
#undef SPLIT_ST
        }
        __syncthreads();

        if (t + 1 < NTILES) {
            const size_t off = (size_t)(t + 1) * BKT;
            if (av0) pa0 = load4<MODE>(pred, aB0 + off);
            if (av1) pa1 = load4<MODE>(pred, aB1 + off);
            if (bv0) pb0 = load4<MODE>(tgt,  bB0 + off);
            if (bv1) pb1 = load4<MODE>(tgt,  bB1 + off);
        }

#pragma unroll
        for (int k8 = 0; k8 < BKT / 8; k8++) {
            const int kc = k8 * 8 + tid4;
            unsigned ah[2][4], al[2][4], bh[2][2], bl[2][2];
#pragma unroll
            for (int mt = 0; mt < 2; mt++) {
                const int r0 = wq * 32 + mt * 16 + g;
                ah[mt][0] = __float_as_uint(Ah[r0][kc]);
                ah[mt][1] = __float_as_uint(Ah[r0 + 8][kc]);
                ah[mt][2] = __float_as_uint(Ah[r0][kc + 4]);
                ah[mt][3] = __float_as_uint(Ah[r0 + 8][kc + 4]);
                al[mt][0] = __float_as_uint(Al[r0][kc]);
                al[mt][1] = __float_as_uint(Al[r0 + 8][kc]);
                al[mt][2] = __float_as_uint(Al[r0][kc + 4]);
                al[mt][3] = __float_as_uint(Al[r0 + 8][kc + 4]);
            }
#pragma unroll
            for (int nt = 0; nt < 2; nt++) {
                const int n0 = wt * 16 + nt * 8 + g;
                bh[nt][0] = __float_as_uint(Bh[n0][kc]);
                bh[nt][1] = __float_as_uint(Bh[n0][kc + 4]);
                bl[nt][0] = __float_as_uint(Bl[n0][kc]);
                bl[nt][1] = __float_as_uint(Bl[n0][kc + 4]);
            }
#pragma unroll
            for (int mt = 0; mt < 2; mt++)
#pragma unroll
                for (int nt = 0; nt < 2; nt++) {
                    mma_tf32(cc[mt][nt], ah[mt], bl[nt]);
                    mma_tf32(cc[mt][nt], al[mt], bh[nt]);
                    mma_tf32(cc[mt][nt], ah[mt], bh[nt]);
                }
        }

        if ((t & (FOLDT - 1)) == (FOLDT - 1)) {
#pragma unroll
            for (int i = 0; i < 2; i++)
#pragma unroll
                for (int j = 0; j < 2; j++)
#pragma unroll
                    for (int r = 0; r < 4; r++) { facc[i][j][r] += cc[i][j][r]; cc[i][j][r] = 0.0f; }
        }
    }

    float* part = g_partial[ks] + (size_t)b * Tn * Qn;
#pragma unroll
    for (int mt = 0; mt < 2; mt++) {
#pragma unroll
        for (int nt = 0; nt < 2; nt++) {
            const float v0 = facc[mt][nt][0] + cc[mt][nt][0];
            const float v1 = facc[mt][nt][1] + cc[mt][nt][1];
            const float v2 = facc[mt][nt][2] + cc[mt][nt][2];
            const float v3 = facc[mt][nt][3] + cc[mt][nt][3];
            const int q_lo = q0 + wq * 32 + mt * 16 + g;
            const int q_hi = q_lo + 8;
            const int t_c  = t0 + wt * 16 + nt * 8 + 2 * tid4;
            if (t_c < Tn) {
                if (q_lo < Qn) part[(size_t)t_c * Qn + q_lo] = v0;
                if (q_hi < Qn) part[(size_t)t_c * Qn + q_hi] = v2;
            }
            if (t_c + 1 < Tn) {
                if (q_lo < Qn) part[(size_t)(t_c + 1) * Qn + q_lo] = v1;
                if (q_hi < Qn) part[(size_t)(t_c + 1) * Qn + q_hi] = v3;
            }
        }
    }
}

__global__ __launch_bounds__(256) void cost_kernel() {
    const int mode = g_mode;
    if (mode == 0)      cost_body<0>();
    else if (mode == 1) cost_body<1>();
    else                cost_body<2>();
}

__global__ void reduce_kernel() {
    const int i = blockIdx.x * blockDim.x + threadIdx.x;
    if (i < COST_N) {
        double s = 0.0;
#pragma unroll
        for (int ks = 0; ks < KSPLIT; ks++) s += (double)g_partial[ks][i];
        g_cost[i] = -(float)s;
    }
}

// ------------------------------ Hungarian ----------------------------------
__global__ __launch_bounds__(32) void hungarian_kernel(float* __restrict__ out, int limit) {
    const int b    = blockIdx.x;
    const int lane = threadIdx.x;
    const float* C = g_cost + (size_t)b * Tn * Qn;

    __shared__ double u[Tn + 1];
    __shared__ double v[Qn + 1];
    __shared__ double minv[Qn + 1];
    __shared__ int    p[Qn + 1];
    __shared__ int    way[Qn + 1];
    __shared__ int    used[Qn + 1];

    const double INFD = INFINITY;

    for (int j = lane; j <= Qn; j += 32) { v[j] = 0.0; p[j] = 0; way[j] = 0; }
    for (int r = lane; r <= Tn; r += 32) u[r] = 0.0;
    __syncwarp();

    for (int i = 1; i <= Tn; i++) {
        if (lane == 0) p[0] = i;
        for (int j = lane; j <= Qn; j += 32) { minv[j] = INFD; used[j] = 0; }
        __syncwarp();

        int j0 = 0;
        for (int step = 0; step <= Qn + 1; step++) {
            if (lane == 0) used[j0] = 1;
            __syncwarp();

            const int i0 = p[j0];
            const double ui0 = u[i0];
            const float* Crow = C + (size_t)(i0 - 1) * Qn;

            double bestv = INFD;
            int    bestj = 0x7fffffff;
            for (int j = lane + 1; j <= Qn; j += 32) {
                if (!used[j]) {
                    const double cur = (double)Crow[j - 1] - ui0 - v[j];
                    if (cur < minv[j]) { minv[j] = cur; way[j] = j0; }
                    const double m = minv[j];
                    if (m < bestv) { bestv = m; bestj = j; }
                }
            }
#pragma unroll
            for (int off = 16; off; off >>= 1) {
                const double ov = __shfl_xor_sync(0xffffffffu, bestv, off);
                const int    oj = __shfl_xor_sync(0xffffffffu, bestj, off);
                if (ov < bestv || (ov == bestv && oj < bestj)) { bestv = ov; bestj = oj; }
            }
            const double delta = bestv;
            const int    j1    = bestj;
            if (j1 < 1 || j1 > Qn) { j0 = 0; break; }
            __syncwarp();

            for (int j2 = lane; j2 <= Qn; j2 += 32) {
                if (used[j2]) {
                    u[p[j2]] += delta;
                    v[j2]    -= delta;
                } else {
                    minv[j2] -= delta;
                }
            }
            __syncwarp();

            j0 = j1;
            if (p[j0] == 0) break;
        }

        if (lane == 0 && j0 != 0) {
            int jj = j0;
            int guard = 0;
            while (jj && guard++ <= Qn) { const int jn = way[jj]; p[jj] = p[jn]; jj = jn; }
        }
        __syncwarp();
    }

    if (lane == 0) {
        int k = 0;
        for (int j = 1; j <= Qn && k < Tn; j++) {
            if (p[j] > 0) {
                const int ip = b * Tn + k;
                const int it = HALF + b * Tn + k;
                if (ip < limit) out[ip] = (float)(j - 1);
                if (it < limit) out[it] = (float)(p[j] - 1);
                k++;
            }
        }
    }
}

extern "C" void kernel_launch(void* const* d_in, const int* in_sizes, int n_in,
                              void* d_out, int out_size) {
    const void* pred = d_in[0];
    const void* tgt  = d_in[1];
    if (n_in >= 2 && in_sizes[0] < in_sizes[1]) {
        const void* t = pred; pred = tgt; tgt = t;
    }
    float* out = (float*)d_out;

    int limit = out_size < OUT_ELEMS ? out_size : OUT_ELEMS;
    if (limit < 1) limit = 1;

    detect_kernel<<<1, 256>>>(tgt);
    zero_out_kernel<<<(limit + 255) / 256, 256>>>(out, limit);

    // Stage host-resident inputs into HBM exactly once.
    stage_kernel<<<4096, 256>>>(pred, 0, (long long)PRED_ELEMS);
    stage_kernel<<<4096, 256>>>(tgt,  1, (long long)TGT_ELEMS);

    dim3 grid((Qn + BM - 1) / BM, (Tn + BN - 1) / BN, Bsz * KSPLIT);  // 8x4x32
    cost_kernel<<<grid, 256>>>();
    reduce_kernel<<<(COST_N + 255) / 256, 256>>>();
    hungarian_kernel<<<Bsz, 32>>>(out, limit);
}

// round 15
// speedup vs baseline: 1.0119x; 1.0119x over previous
#include <cuda_runtime.h>
#include <cuda_bf16.h>
#include <cuda_fp16.h>
#include <math.h>

// Output contract (proven): float32 indices, [0,1600) pred_idx, [1600,3200) tgt_idx.
// R14 findings: inputs are DEVICE-resident fp32 (stage ran at 6.5TB/s);
// cost_kernel itself is ~31.5ms (10x over model) -> suspected local-memory
// demotion of mma operand arrays.  This round: fully scalarized mma path,
// and cost_kernel placed at launch index 3 (the profiled slot).

#define Bsz 8
#define Qn  500
#define Tn  200
#define HWn 65536
#define OUT_ELEMS (2 * Bsz * Tn)
#define HALF      (Bsz * Tn)
#define KSPLIT 4
#define KSC (HWn / KSPLIT)         // 16384
#define COST_N (Bsz * Tn * Qn)     // 800000

#define BM 64
#define BN 64
#define BKT 32
#define LDA (BKT + 4)              // 36 floats: conflict-free fragment columns
#define NTILES (KSC / BKT)         // 512
#define FOLDT 8

__device__ float g_cost[COST_N];
__device__ float g_partial[KSPLIT][COST_N];
__device__ int   g_mode;           // 0=fp32, 1=bf16, 2=fp16

__device__ __forceinline__ float fsigmoid(float x) {
    return __fdividef(1.0f, 1.0f + __expf(-x));
}
__device__ __forceinline__ unsigned tf32_of(float x) {
    unsigned r;
    asm("cvt.rna.tf32.f32 %0, %1;" : "=r"(r) : "f"(x));
    return r;
}
#define U(x) __float_as_uint(x)

// mma on NAMED scalars only -- nothing addressable.
#define MMA(c0,c1,c2,c3, a0,a1,a2,a3, b0,b1)                                 \
    asm volatile("mma.sync.aligned.m16n8k8.row.col.f32.tf32.tf32.f32 "       \
                 "{%0,%1,%2,%3}, {%4,%5,%6,%7}, {%8,%9}, {%0,%1,%2,%3};"     \
                 : "+f"(c0), "+f"(c1), "+f"(c2), "+f"(c3)                    \
                 : "r"(a0), "r"(a1), "r"(a2), "r"(a3), "r"(b0), "r"(b1))

// --------------------------- dtype detector --------------------------------
#define DET_WORDS 16384
__global__ void detect_kernel(const void* tgt) {
    __shared__ int s_bf, s_fh;
    if (threadIdx.x == 0) { s_bf = 0; s_fh = 0; }
    __syncthreads();
    const unsigned int* w = (const unsigned int*)tgt;
    int bf = 0, fh = 0;
    for (int i = threadIdx.x; i < DET_WORDS; i += 256) {
        const unsigned int b1 = (w[i] >> 8) & 0xff;
        if (b1 == 0x3E || b1 == 0x3F) bf++;
        else if (b1 >= 0x30 && b1 <= 0x3B) fh++;
    }
    atomicAdd(&s_bf, bf);
    atomicAdd(&s_fh, fh);
    __syncthreads();
    if (threadIdx.x == 0) {
        if      (s_bf > DET_WORDS / 2) g_mode = 1;
        else if (s_fh > DET_WORDS / 2) g_mode = 2;
        else                           g_mode = 0;
    }
}

__global__ void nop_kernel() {}

template <int MODE>
__device__ __forceinline__ float4 load4(const void* base, size_t elemIdx) {
    if (MODE == 0) {
        return *(const float4*)((const float*)base + elemIdx);
    } else if (MODE == 1) {
        const __nv_bfloat162* p = (const __nv_bfloat162*)((const __nv_bfloat16*)base + elemIdx);
        const __nv_bfloat162 a = p[0], b = p[1];
        return make_float4(__bfloat162float(a.x), __bfloat162float(a.y),
                           __bfloat162float(b.x), __bfloat162float(b.y));
    } else {
        const __half2* p = (const __half2*)((const __half*)base + elemIdx);
        const __half2 a = p[0], b = p[1];
        return make_float4(__half2float(a.x), __half2float(a.y),
                           __half2float(b.x), __half2float(b.y));
    }
}

// ------------------------------ cost GEMM (3xTF32, scalarized) -------------
template <int MODE>
__device__ void cost_body(const void* __restrict__ pred, const void* __restrict__ tgt) {
    __shared__ float Ah[BM][LDA], Al[BM][LDA];
    __shared__ float Bh[BN][LDA], Bl[BN][LDA];

    const int b  = blockIdx.z / KSPLIT;
    const int ks = blockIdx.z % KSPLIT;
    const int q0 = blockIdx.x * BM;
    const int t0 = blockIdx.y * BN;
    const int tid  = threadIdx.x;
    const int lane = tid & 31;
    const int warp = tid >> 5;
    const int wq = warp & 1;
    const int wt = warp >> 1;
    const int g    = lane >> 2;
    const int tid4 = lane & 3;

    const int lrow0 = tid >> 3;
    const int lrow1 = lrow0 + 32;
    const int lk4   = (tid & 7) * 4;
    const bool av0 = (q0 + lrow0) < Qn, av1 = (q0 + lrow1) < Qn;
    const bool bv0 = (t0 + lrow0) < Tn, bv1 = (t0 + lrow1) < Tn;
    const size_t kbase = (size_t)ks * KSC + lk4;
    const size_t aB0 = ((size_t)b * Qn + (av0 ? (q0 + lrow0) : 0)) * HWn + kbase;
    const size_t aB1 = ((size_t)b * Qn + (av1 ? (q0 + lrow1) : 0)) * HWn + kbase;
    const size_t bB0 = ((size_t)b * Tn + (bv0 ? (t0 + lrow0) : 0)) * HWn + kbase;
    const size_t bB1 = ((size_t)b * Tn + (bv1 ? (t0 + lrow1) : 0)) * HWn + kbase;

    // Window accumulators (named) and fp32 masters (named).
    float c00_0=0,c00_1=0,c00_2=0,c00_3=0, c01_0=0,c01_1=0,c01_2=0,c01_3=0,
          c10_0=0,c10_1=0,c10_2=0,c10_3=0, c11_0=0,c11_1=0,c11_2=0,c11_3=0;
    float m00_0=0,m00_1=0,m00_2=0,m00_3=0, m01_0=0,m01_1=0,m01_2=0,m01_3=0,
          m10_0=0,m10_1=0,m10_2=0,m10_3=0, m11_0=0,m11_1=0,m11_2=0,m11_3=0;

    float4 pa0 = av0 ? load4<MODE>(pred, aB0) : make_float4(0,0,0,0);
    float4 pa1 = av1 ? load4<MODE>(pred, aB1) : make_float4(0,0,0,0);
    float4 pb0 = bv0 ? load4<MODE>(tgt,  bB0) : make_float4(0,0,0,0);
    float4 pb1 = bv1 ? load4<MODE>(tgt,  bB1) : make_float4(0,0,0,0);

    for (int t = 0; t < NTILES; t++) {
        float s0x=0,s0y=0,s0z=0,s0w=0, s1x=0,s1y=0,s1z=0,s1w=0;
        if (av0) { s0x=fsigmoid(pa0.x); s0y=fsigmoid(pa0.y); s0z=fsigmoid(pa0.z); s0w=fsigmoid(pa0.w); }
        if (av1) { s1x=fsigmoid(pa1.x); s1y=fsigmoid(pa1.y); s1z=fsigmoid(pa1.z); s1w=fsigmoid(pa1.w); }

        __syncthreads();
        {
            float* ah0 = &Ah[lrow0][lk4]; float* al0 = &Al[lrow0][lk4];
            float* ah1 = &Ah[lrow1][lk4]; float* al1 = &Al[lrow1][lk4];
#define SPLIT_ST(dsth, dstl, v, idx) { float hf = __uint_as_float(tf32_of(v)); \
        (dsth)[idx] = hf; (dstl)[idx] = __uint_as_float(tf32_of((v) - hf)); }
            SPLIT_ST(ah0, al0, s0x, 0) SPLIT_ST(ah0, al0, s0y, 1)
            SPLIT_ST(ah0, al0, s0z, 2) SPLIT_ST(ah0, al0, s0w, 3)
            SPLIT_ST(ah1, al1, s1x, 0) SPLIT_ST(ah1, al1, s1y, 1)
            SPLIT_ST(ah1, al1, s1z, 2) SPLIT_ST(ah1, al1, s1w, 3)
            float* bh0 = &Bh[lrow0][lk4]; float* bl0 = &Bl[lrow0][lk4];
            float* bh1 = &Bh[lrow1][lk4]; float* bl1 = &Bl[lrow1][lk4];
            float t0x = bv0?pb0.x:0, t0y = bv0?pb0.y:0, t0z = bv0?pb0.z:0, t0w = bv0?pb0.w:0;
            float t1x = bv1?pb1.x:0, t1y = bv1?pb1.y:0, t1z = bv1?pb1.z:0, t1w = bv1?pb1.w:0;
            SPLIT_ST(bh0, bl0, t0x, 0) SPLIT_ST(bh0, bl0, t0y, 1)
            SPLIT_ST(bh0, bl0, t0z, 2) SPLIT_ST(bh0, bl0, t0w, 3)
            SPLIT_ST(bh1, bl1, t1x, 0) SPLIT_ST(bh1, bl1, t1y, 1)
            SPLIT_ST(bh1, bl1, t1z, 2) SPLIT_ST(bh1, bl1, t1w, 3)
#undef SPLIT_ST
        }
        __syncthreads();

        if (t + 1 < NTILES) {
            const size_t off = (size_t)(t + 1) * BKT;
            if (av0) pa0 = load4<MODE>(pred, aB0 + off);
            if (av1) pa1 = load4<MODE>(pred, aB1 + off);
            if (bv0) pb0 = load4<MODE>(tgt,  bB0 + off);
            if (bv1) pb1 = load4<MODE>(tgt,  bB1 + off);
        }

        const int r0 = wq * 32 + g;
        const int r1 = r0 + 16;
        const int n0 = wt * 16 + g;
        const int n1 = n0 + 8;
#pragma unroll
        for (int k8 = 0; k8 < BKT / 8; k8++) {
            const int kc = k8 * 8 + tid4;
            // A fragments (hi, lo), named.
            const unsigned a00=U(Ah[r0][kc]), a01=U(Ah[r0+8][kc]), a02=U(Ah[r0][kc+4]), a03=U(Ah[r0+8][kc+4]);
            const unsigned a10=U(Ah[r1][kc]), a11=U(Ah[r1+8][kc]), a12=U(Ah[r1][kc+4]), a13=U(Ah[r1+8][kc+4]);
            const unsigned l00=U(Al[r0][kc]), l01=U(Al[r0+8][kc]), l02=U(Al[r0][kc+4]), l03=U(Al[r0+8][kc+4]);
            const unsigned l10=U(Al[r1][kc]), l11=U(Al[r1+8][kc]), l12=U(Al[r1][kc+4]), l13=U(Al[r1+8][kc+4]);
            // B fragments (hi, lo), named.
            const unsigned p00=U(Bh[n0][kc]), p01=U(Bh[n0][kc+4]);
            const unsigned p10=U(Bh[n1][kc]), p11=U(Bh[n1][kc+4]);
            const unsigned q00=U(Bl[n0][kc]), q01=U(Bl[n0][kc+4]);
            const unsigned q10=U(Bl[n1][kc]), q11=U(Bl[n1][kc+4]);

            // 3xTF32: hi*lo + lo*hi + hi*hi
            MMA(c00_0,c00_1,c00_2,c00_3, a00,a01,a02,a03, q00,q01);
            MMA(c00_0,c00_1,c00_2,c00_3, l00,l01,l02,l03, p00,p01);
            MMA(c00_0,c00_1,c00_2,c00_3, a00,a01,a02,a03, p00,p01);

            MMA(c01_0,c01_1,c01_2,c01_3, a00,a01,a02,a03, q10,q11);
            MMA(c01_0,c01_1,c01_2,c01_3, l00,l01,l02,l03, p10,p11);
            MMA(c01_0,c01_1,c01_2,c01_3, a00,a01,a02,a03, p10,p11);

            MMA(c10_0,c10_1,c10_2,c10_3, a10,a11,a12,a13, q00,q01);
            MMA(c10_0,c10_1,c10_2,c10_3, l10,l11,l12,l13, p00,p01);
            MMA(c10_0,c10_1,c10_2,c10_3, a10,a11,a12,a13, p00,p01);

            MMA(c11_0,c11_1,c11_2,c11_3, a10,a11,a12,a13, q10,q11);
            MMA(c11_0,c11_1,c11_2,c11_3, l10,l11,l12,l13, p10,p11);
            MMA(c11_0,c11_1,c11_2,c11_3, a10,a11,a12,a13, p10,p11);
        }

        if ((t & (FOLDT - 1)) == (FOLDT - 1)) {
            m00_0+=c00_0; m00_1+=c00_1; m00_2+=c00_2; m00_3+=c00_3;
            m01_0+=c01_0; m01_1+=c01_1; m01_2+=c01_2; m01_3+=c01_3;
            m10_0+=c10_0; m10_1+=c10_1; m10_2+=c10_2; m10_3+=c10_3;
            m11_0+=c11_0; m11_1+=c11_1; m11_2+=c11_2; m11_3+=c11_3;
            c00_0=0;c00_1=0;c00_2=0;c00_3=0; c01_0=0;c01_1=0;c01_2=0;c01_3=0;
            c10_0=0;c10_1=0;c10_2=0;c10_3=0; c11_0=0;c11_1=0;c11_2=0;c11_3=0;
        }
    }

    float* part = g_partial[ks] + (size_t)b * Tn * Qn;
#define EMIT(MT, NT, V0, V1, V2, V3)                                         \
    {                                                                        \
        const int q_lo = q0 + wq * 32 + (MT) * 16 + g;                       \
        const int q_hi = q_lo + 8;                                           \
        const int t_c  = t0 + wt * 16 + (NT) * 8 + 2 * tid4;                 \
        if (t_c < Tn) {                                                      \
            if (q_lo < Qn) part[(size_t)t_c * Qn + q_lo] = (V0);             \
            if (q_hi < Qn) part[(size_t)t_c * Qn + q_hi] = (V2);             \
        }                                                                    \
        if (t_c + 1 < Tn) {                                                  \
            if (q_lo < Qn) part[(size_t)(t_c + 1) * Qn + q_lo] = (V1);       \
            if (q_hi < Qn) part[(size_t)(t_c + 1) * Qn + q_hi] = (V3);       \
        }                                                                    \
    }
    EMIT(0, 0, m00_0 + c00_0, m00_1 + c00_1, m00_2 + c00_2, m00_3 + c00_3)
    EMIT(0, 1, m01_0 + c01_0, m01_1 + c01_1, m01_2 + c01_2, m01_3 + c01_3)
    EMIT(1, 0, m10_0 + c10_0, m10_1 + c10_1, m10_2 + c10_2, m10_3 + c10_3)
    EMIT(1, 1, m11_0 + c11_0, m11_1 + c11_1, m11_2 + c11_2, m11_3 + c11_3)
#undef EMIT
}

__global__ __launch_bounds__(256) void cost_kernel(const void* __restrict__ pred,
                                                   const void* __restrict__ tgt) {
    const int mode = g_mode;
    if (mode == 0)      cost_body<0>(pred, tgt);
    else if (mode == 1) cost_body<1>(pred, tgt);
    else                cost_body<2>(pred, tgt);
}

__global__ void reduce_kernel() {
    const int i = blockIdx.x * blockDim.x + threadIdx.x;
    if (i < COST_N) {
        double s = 0.0;
#pragma unroll
        for (int ks = 0; ks < KSPLIT; ks++) s += (double)g_partial[ks][i];
        g_cost[i] = -(float)s;
    }
}

// ------------------------------ Hungarian ----------------------------------
__global__ __launch_bounds__(32) void hungarian_kernel(float* __restrict__ out, int limit) {
    const int b    = blockIdx.x;
    const int lane = threadIdx.x;
    const float* C = g_cost + (size_t)b * Tn * Qn;

    __shared__ double u[Tn + 1];
    __shared__ double v[Qn + 1];
    __shared__ double minv[Qn + 1];
    __shared__ int    p[Qn + 1];
    __shared__ int    way[Qn + 1];
    __shared__ int    used[Qn + 1];

    const double INFD = INFINITY;

    for (int j = lane; j <= Qn; j += 32) { v[j] = 0.0; p[j] = 0; way[j] = 0; }
    for (int r = lane; r <= Tn; r += 32) u[r] = 0.0;
    __syncwarp();

    for (int i = 1; i <= Tn; i++) {
        if (lane == 0) p[0] = i;
        for (int j = lane; j <= Qn; j += 32) { minv[j] = INFD; used[j] = 0; }
        __syncwarp();

        int j0 = 0;
        for (int step = 0; step <= Qn + 1; step++) {
            if (lane == 0) used[j0] = 1;
            __syncwarp();

            const int i0 = p[j0];
            const double ui0 = u[i0];
            const float* Crow = C + (size_t)(i0 - 1) * Qn;

            double bestv = INFD;
            int    bestj = 0x7fffffff;
            for (int j = lane + 1; j <= Qn; j += 32) {
                if (!used[j]) {
                    const double cur = (double)Crow[j - 1] - ui0 - v[j];
                    if (cur < minv[j]) { minv[j] = cur; way[j] = j0; }
                    const double m = minv[j];
                    if (m < bestv) { bestv = m; bestj = j; }
                }
            }
#pragma unroll
            for (int off = 16; off; off >>= 1) {
                const double ov = __shfl_xor_sync(0xffffffffu, bestv, off);
                const int    oj = __shfl_xor_sync(0xffffffffu, bestj, off);
                if (ov < bestv || (ov == bestv && oj < bestj)) { bestv = ov; bestj = oj; }
            }
            const double delta = bestv;
            const int    j1    = bestj;
            if (j1 < 1 || j1 > Qn) { j0 = 0; break; }
            __syncwarp();

            for (int j2 = lane; j2 <= Qn; j2 += 32) {
                if (used[j2]) {
                    u[p[j2]] += delta;
                    v[j2]    -= delta;
                } else {
                    minv[j2] -= delta;
                }
            }
            __syncwarp();

            j0 = j1;
            if (p[j0] == 0) break;
        }

        if (lane == 0 && j0 != 0) {
            int jj = j0;
            int guard = 0;
            while (jj && guard++ <= Qn) { const int jn = way[jj]; p[jj] = p[jn]; jj = jn; }
        }
        __syncwarp();
    }

    if (lane == 0) {
        int k = 0;
        for (int j = 1; j <= Qn && k < Tn; j++) {
            if (p[j] > 0) {
                const int ip = b * Tn + k;
                const int it = HALF + b * Tn + k;
                if (ip < limit) out[ip] = (float)(j - 1);
                if (it < limit) out[it] = (float)(p[j] - 1);
                k++;
            }
        }
    }
}

extern "C" void kernel_launch(void* const* d_in, const int* in_sizes, int n_in,
                              void* d_out, int out_size) {
    const void* pred = d_in[0];
    const void* tgt  = d_in[1];
    if (n_in >= 2 && in_sizes[0] < in_sizes[1]) {
        const void* t = pred; pred = tgt; tgt = t;
    }
    float* out = (float*)d_out;

    int limit = out_size < OUT_ELEMS ? out_size : OUT_ELEMS;
    if (limit < 1) limit = 1;

    // Launch order chosen so cost_kernel sits at index 3 (the profiled slot).
    detect_kernel<<<1, 256>>>(tgt);                                   // 0
    nop_kernel<<<1, 32>>>();                                          // 1
    nop_kernel<<<1, 32>>>();                                          // 2
    dim3 grid((Qn + BM - 1) / BM, (Tn + BN - 1) / BN, Bsz * KSPLIT);  // 8x4x32
    cost_kernel<<<grid, 256>>>(pred, tgt);                            // 3
    reduce_kernel<<<(COST_N + 255) / 256, 256>>>();                   // 4
    hungarian_kernel<<<Bsz, 32>>>(out, limit);                        // 5
}